// round 1
// baseline (speedup 1.0000x reference)
#include <cuda_runtime.h>
#include <math.h>

#define NND    6144
#define NFEAT  512
#define NHID   256
#define NCLASS 8
#define ADIM   128

// ---------------- device scratch (no allocations allowed) ----------------
__device__ float g_zcat[NND * 384];
__device__ float g_nzT[3 * NND];
__device__ float g_adj[(size_t)NND * NND];
__device__ float g_fW1[NND * NHID];
__device__ float g_x[NND * NHID];
__device__ float g_Q[NND * NHID];
__device__ float g_K[NND * NHID];
__device__ float g_V[NND * NHID];
__device__ float g_att[(size_t)NND * NND];
__device__ float g_xt[NND * NHID];
__device__ float g_xtw2[NND * NCLASS];

// ---------------- generic tiled SGEMM ----------------
struct GemmArgs {
    const float* A[3];
    const float* B[3];
    float*       C[3];
    const float* bias[3];
    const float* mul;     // optional elementwise multiplier, same layout as C
    int M, N, K, lda, ldb, ldc, act;   // act: 0 none, 1 relu
};

// C = act( (A @ B) * mul + bias ).  A row-major [M,K]; B row-major [K,N]
// (TRANSB=false) or [N,K] (TRANSB=true, i.e. C = A @ B^T). All dims must be
// divisible by the tile sizes (true for every launch here).
template <int BM, int BN, int BK, int TM, int TN, bool TRANSB>
__global__ void __launch_bounds__((BM / TM) * (BN / TN))
sgemm_k(const GemmArgs p) {
    constexpr int NT = (BM / TM) * (BN / TN);
    constexpr int LA = (BM * BK) / (4 * NT);
    constexpr int LB = (BK * BN) / (4 * NT);
    static_assert(LA >= 1 && LB >= 1, "tile too small");
    static_assert(TM == 8 && TN == 8, "microtile fixed at 8x8");

    const int bz = blockIdx.z;
    const float* __restrict__ A    = p.A[bz];
    const float* __restrict__ B    = p.B[bz];
    float* __restrict__       C    = p.C[bz];
    const float* __restrict__ bias = p.bias[bz];

    __shared__ float As[BK][BM];
    __shared__ float Bs[BK][BN];

    const int tid = threadIdx.x;
    const int m0  = blockIdx.x * BM;
    const int n0  = blockIdx.y * BN;
    constexpr int TCOLS = BN / TN;
    const int tc = tid % TCOLS;
    const int tr = tid / TCOLS;

    const int lda = p.lda, ldb = p.ldb, K = p.K;

    float acc[TM][TN];
#pragma unroll
    for (int i = 0; i < TM; i++)
#pragma unroll
        for (int j = 0; j < TN; j++) acc[i][j] = 0.f;

    float4 ra[LA], rb[LB];

    auto loadA = [&](int k0) {
#pragma unroll
        for (int l = 0; l < LA; l++) {
            int idx = tid + l * NT;
            int row = idx / (BK / 4);
            int k4  = (idx % (BK / 4)) * 4;
            ra[l] = *reinterpret_cast<const float4*>(&A[(size_t)(m0 + row) * lda + k0 + k4]);
        }
    };
    auto loadB = [&](int k0) {
#pragma unroll
        for (int l = 0; l < LB; l++) {
            int idx = tid + l * NT;
            if (!TRANSB) {
                int krow = idx / (BN / 4);
                int nc4  = (idx % (BN / 4)) * 4;
                rb[l] = *reinterpret_cast<const float4*>(&B[(size_t)(k0 + krow) * ldb + n0 + nc4]);
            } else {
                int nrow = idx / (BK / 4);
                int k4   = (idx % (BK / 4)) * 4;
                rb[l] = *reinterpret_cast<const float4*>(&B[(size_t)(n0 + nrow) * ldb + k0 + k4]);
            }
        }
    };
    auto storeA = [&]() {
#pragma unroll
        for (int l = 0; l < LA; l++) {
            int idx = tid + l * NT;
            int row = idx / (BK / 4);
            int k4  = (idx % (BK / 4)) * 4;
            As[k4 + 0][row] = ra[l].x;
            As[k4 + 1][row] = ra[l].y;
            As[k4 + 2][row] = ra[l].z;
            As[k4 + 3][row] = ra[l].w;
        }
    };
    auto storeB = [&]() {
#pragma unroll
        for (int l = 0; l < LB; l++) {
            int idx = tid + l * NT;
            if (!TRANSB) {
                int krow = idx / (BN / 4);
                int nc4  = (idx % (BN / 4)) * 4;
                *reinterpret_cast<float4*>(&Bs[krow][nc4]) = rb[l];
            } else {
                int nrow = idx / (BK / 4);
                int k4   = (idx % (BK / 4)) * 4;
                Bs[k4 + 0][nrow] = rb[l].x;
                Bs[k4 + 1][nrow] = rb[l].y;
                Bs[k4 + 2][nrow] = rb[l].z;
                Bs[k4 + 3][nrow] = rb[l].w;
            }
        }
    };
    auto compute = [&]() {
#pragma unroll
        for (int kk = 0; kk < BK; kk++) {
            float ar[TM], br[TN];
            *reinterpret_cast<float4*>(&ar[0]) = *reinterpret_cast<const float4*>(&As[kk][tr * 4]);
            *reinterpret_cast<float4*>(&ar[4]) = *reinterpret_cast<const float4*>(&As[kk][BM / 2 + tr * 4]);
            *reinterpret_cast<float4*>(&br[0]) = *reinterpret_cast<const float4*>(&Bs[kk][tc * 4]);
            *reinterpret_cast<float4*>(&br[4]) = *reinterpret_cast<const float4*>(&Bs[kk][BN / 2 + tc * 4]);
#pragma unroll
            for (int i = 0; i < TM; i++)
#pragma unroll
                for (int j = 0; j < TN; j++) acc[i][j] = fmaf(ar[i], br[j], acc[i][j]);
        }
    };

    loadA(0);
    loadB(0);
    storeA();
    storeB();
    __syncthreads();
    for (int k0 = BK; k0 < K; k0 += BK) {
        loadA(k0);
        loadB(k0);
        compute();
        __syncthreads();
        storeA();
        storeB();
        __syncthreads();
    }
    compute();

    const int ldc = p.ldc;
    const float* __restrict__ mul = p.mul;
#pragma unroll
    for (int i = 0; i < TM; i++) {
        int m = m0 + ((i < 4) ? (tr * 4 + i) : (BM / 2 + tr * 4 + (i - 4)));
#pragma unroll
        for (int jh = 0; jh < 2; jh++) {
            int n = n0 + ((jh == 0) ? tc * 4 : (BN / 2 + tc * 4));
            float4 v;
            v.x = acc[i][jh * 4 + 0];
            v.y = acc[i][jh * 4 + 1];
            v.z = acc[i][jh * 4 + 2];
            v.w = acc[i][jh * 4 + 3];
            if (mul) {
                float4 mv = *reinterpret_cast<const float4*>(&mul[(size_t)m * ldc + n]);
                v.x *= mv.x; v.y *= mv.y; v.z *= mv.z; v.w *= mv.w;
            }
            if (bias) {
                v.x += bias[n - n0 + 0 + (n0 ? 0 : 0)];  // bias indexed by column within C
                v.x += 0.f;  // (kept simple below)
            }
            // NOTE: bias indexing must be by absolute output column of this C
            if (bias) {
                // undo the placeholder add above: recompute cleanly
            }
            *reinterpret_cast<float4*>(&C[(size_t)m * ldc + n]) = v;
            if (bias || p.act == 1) {
                // reload-free epilogue done properly below
            }
        }
    }
    // ---- clean epilogue (bias/act) done in the loop above would be messy with
    // the placeholder; redo stores properly here if bias/act present.
    if (bias || p.act == 1) {
#pragma unroll
        for (int i = 0; i < TM; i++) {
            int m = m0 + ((i < 4) ? (tr * 4 + i) : (BM / 2 + tr * 4 + (i - 4)));
#pragma unroll
            for (int jh = 0; jh < 2; jh++) {
                int n = n0 + ((jh == 0) ? tc * 4 : (BN / 2 + tc * 4));
                float4 v;
                v.x = acc[i][jh * 4 + 0];
                v.y = acc[i][jh * 4 + 1];
                v.z = acc[i][jh * 4 + 2];
                v.w = acc[i][jh * 4 + 3];
                if (mul) {
                    float4 mv = *reinterpret_cast<const float4*>(&mul[(size_t)m * ldc + n]);
                    v.x *= mv.x; v.y *= mv.y; v.z *= mv.z; v.w *= mv.w;
                }
                if (bias) {
                    v.x += bias[n + 0];
                    v.y += bias[n + 1];
                    v.z += bias[n + 2];
                    v.w += bias[n + 3];
                }
                if (p.act == 1) {
                    v.x = fmaxf(v.x, 0.f); v.y = fmaxf(v.y, 0.f);
                    v.z = fmaxf(v.z, 0.f); v.w = fmaxf(v.w, 0.f);
                }
                *reinterpret_cast<float4*>(&C[(size_t)m * ldc + n]) = v;
            }
        }
    }
}

// ---------------- gate: z4 = zcat @ Wagg + bagg ; nz = softmax(z4) ----------------
__global__ void agg_softmax_k(const float* __restrict__ Wagg, const float* __restrict__ bagg,
                              float* __restrict__ out_nz, int write_out) {
    int row  = blockIdx.x * (blockDim.x / 32) + (threadIdx.x >> 5);
    int lane = threadIdx.x & 31;
    if (row >= NND) return;
    const float* z = &g_zcat[(size_t)row * 384];
    float s0 = 0.f, s1 = 0.f, s2 = 0.f;
    for (int k = lane; k < 384; k += 32) {
        float v = z[k];
        s0 = fmaf(v, Wagg[k * 3 + 0], s0);
        s1 = fmaf(v, Wagg[k * 3 + 1], s1);
        s2 = fmaf(v, Wagg[k * 3 + 2], s2);
    }
#pragma unroll
    for (int off = 16; off; off >>= 1) {
        s0 += __shfl_down_sync(0xffffffffu, s0, off);
        s1 += __shfl_down_sync(0xffffffffu, s1, off);
        s2 += __shfl_down_sync(0xffffffffu, s2, off);
    }
    if (lane == 0) {
        s0 += bagg[0]; s1 += bagg[1]; s2 += bagg[2];
        float mx = fmaxf(s0, fmaxf(s1, s2));
        float e0 = expf(s0 - mx), e1 = expf(s1 - mx), e2 = expf(s2 - mx);
        float inv = 1.f / (e0 + e1 + e2);
        e0 *= inv; e1 *= inv; e2 *= inv;
        g_nzT[0 * NND + row] = e0;
        g_nzT[1 * NND + row] = e1;
        g_nzT[2 * NND + row] = e2;
        if (write_out) {
            out_nz[row * 3 + 0] = e0;
            out_nz[row * 3 + 1] = e1;
            out_nz[row * 3 + 2] = e2;
        }
    }
}

// ---------------- adj[i,j] = nz[j,0]*a0 + nz[j,1]*a1 + nz[j,2]*a2 ----------------
__global__ void build_adj_k(const float* __restrict__ a0, const float* __restrict__ a1,
                            const float* __restrict__ a2) {
    const size_t total4 = (size_t)NND * NND / 4;
    for (size_t e = (size_t)blockIdx.x * blockDim.x + threadIdx.x; e < total4;
         e += (size_t)gridDim.x * blockDim.x) {
        size_t off = e * 4;
        int j = (int)(off % NND);
        float4 w0 = *reinterpret_cast<const float4*>(&g_nzT[j]);
        float4 w1 = *reinterpret_cast<const float4*>(&g_nzT[NND + j]);
        float4 w2 = *reinterpret_cast<const float4*>(&g_nzT[2 * NND + j]);
        float4 x0 = *reinterpret_cast<const float4*>(a0 + off);
        float4 x1 = *reinterpret_cast<const float4*>(a1 + off);
        float4 x2 = *reinterpret_cast<const float4*>(a2 + off);
        float4 r;
        r.x = w0.x * x0.x + w1.x * x1.x + w2.x * x2.x;
        r.y = w0.y * x0.y + w1.y * x1.y + w2.y * x2.y;
        r.z = w0.z * x0.z + w1.z * x1.z + w2.z * x2.z;
        r.w = w0.w * x0.w + w1.w * x1.w + w2.w * x2.w;
        *reinterpret_cast<float4*>(&g_adj[off]) = r;
    }
}

// ---------------- per-row softmax over the 6144-wide attention matrix -----------
// (gcn_norm is the identity to <1e-5: softmax row sums are 1 +- 5e-6 and
//  rsqrt(1+1e-9) rounds to 1 in fp32, so dinv_i*dinv_j == 1)
__global__ void attn_softmax_k() {
    const int row = blockIdx.x;
    float* __restrict__ ptr = &g_att[(size_t)row * NND];
    const int tid  = threadIdx.x;
    const int lane = tid & 31, warp = tid >> 5;
    float4 v[6];
    float mx = -3.4e38f;
#pragma unroll
    for (int l = 0; l < 6; l++) {
        v[l] = *reinterpret_cast<const float4*>(&ptr[(tid + l * 256) * 4]);
        mx = fmaxf(mx, fmaxf(fmaxf(v[l].x, v[l].y), fmaxf(v[l].z, v[l].w)));
    }
    __shared__ float sm[8], ss[8];
#pragma unroll
    for (int off = 16; off; off >>= 1) mx = fmaxf(mx, __shfl_xor_sync(0xffffffffu, mx, off));
    if (lane == 0) sm[warp] = mx;
    __syncthreads();
    float bm = fmaxf(fmaxf(fmaxf(sm[0], sm[1]), fmaxf(sm[2], sm[3])),
                     fmaxf(fmaxf(sm[4], sm[5]), fmaxf(sm[6], sm[7])));
    float sum = 0.f;
#pragma unroll
    for (int l = 0; l < 6; l++) {
        v[l].x = expf(v[l].x - bm);
        v[l].y = expf(v[l].y - bm);
        v[l].z = expf(v[l].z - bm);
        v[l].w = expf(v[l].w - bm);
        sum += v[l].x + v[l].y + v[l].z + v[l].w;
    }
#pragma unroll
    for (int off = 16; off; off >>= 1) sum += __shfl_xor_sync(0xffffffffu, sum, off);
    if (lane == 0) ss[warp] = sum;
    __syncthreads();
    float tot = ss[0] + ss[1] + ss[2] + ss[3] + ss[4] + ss[5] + ss[6] + ss[7];
    float scale = 1.f / tot;
#pragma unroll
    for (int l = 0; l < 6; l++) {
        v[l].x *= scale; v[l].y *= scale; v[l].z *= scale; v[l].w *= scale;
        *reinterpret_cast<float4*>(&ptr[(tid + l * 256) * 4]) = v[l];
    }
}

// ---------------- X_tilde @ W2 (skinny, N=8) ----------------
__global__ void xtw2_k(const float* __restrict__ W2) {
    int row  = blockIdx.x * 8 + (threadIdx.x >> 5);
    int lane = threadIdx.x & 31;
    if (row >= NND) return;
    const float* xr = &g_xt[(size_t)row * NHID];
    float acc[8] = {0, 0, 0, 0, 0, 0, 0, 0};
    for (int h = lane; h < NHID; h += 32) {
        float xv = xr[h];
        const float4* wp = reinterpret_cast<const float4*>(&W2[h * 8]);
        float4 wlo = wp[0], whi = wp[1];
        acc[0] = fmaf(xv, wlo.x, acc[0]);
        acc[1] = fmaf(xv, wlo.y, acc[1]);
        acc[2] = fmaf(xv, wlo.z, acc[2]);
        acc[3] = fmaf(xv, wlo.w, acc[3]);
        acc[4] = fmaf(xv, whi.x, acc[4]);
        acc[5] = fmaf(xv, whi.y, acc[5]);
        acc[6] = fmaf(xv, whi.z, acc[6]);
        acc[7] = fmaf(xv, whi.w, acc[7]);
    }
#pragma unroll
    for (int c = 0; c < 8; c++)
#pragma unroll
        for (int off = 16; off; off >>= 1) acc[c] += __shfl_down_sync(0xffffffffu, acc[c], off);
    if (lane == 0) {
#pragma unroll
        for (int c = 0; c < 8; c++) g_xtw2[row * 8 + c] = acc[c];
    }
}

// ---------------- z = adj @ xtw2 + b2 ; out = softmax(z, axis=1). 8 rows/CTA ----
__global__ void final_k(const float* __restrict__ b2, float* __restrict__ out) {
    const int r0  = blockIdx.x * 8;
    const int tid = threadIdx.x;
    float acc[8][8];
#pragma unroll
    for (int r = 0; r < 8; r++)
#pragma unroll
        for (int c = 0; c < 8; c++) acc[r][c] = 0.f;

    for (int j4 = tid; j4 < NND / 4; j4 += 256) {
        float4 w[8];
        const float4* wp = reinterpret_cast<const float4*>(&g_xtw2[(size_t)j4 * 32]);
#pragma unroll
        for (int q = 0; q < 8; q++) w[q] = wp[q];
#pragma unroll
        for (int r = 0; r < 8; r++) {
            float4 a = *reinterpret_cast<const float4*>(&g_adj[(size_t)(r0 + r) * NND + j4 * 4]);
            float av[4] = {a.x, a.y, a.z, a.w};
#pragma unroll
            for (int q = 0; q < 4; q++) {
                acc[r][0] = fmaf(av[q], w[2 * q].x, acc[r][0]);
                acc[r][1] = fmaf(av[q], w[2 * q].y, acc[r][1]);
                acc[r][2] = fmaf(av[q], w[2 * q].z, acc[r][2]);
                acc[r][3] = fmaf(av[q], w[2 * q].w, acc[r][3]);
                acc[r][4] = fmaf(av[q], w[2 * q + 1].x, acc[r][4]);
                acc[r][5] = fmaf(av[q], w[2 * q + 1].y, acc[r][5]);
                acc[r][6] = fmaf(av[q], w[2 * q + 1].z, acc[r][6]);
                acc[r][7] = fmaf(av[q], w[2 * q + 1].w, acc[r][7]);
            }
        }
    }

    __shared__ float sred[8][64];
    const int lane = tid & 31, warp = tid >> 5;
#pragma unroll
    for (int r = 0; r < 8; r++)
#pragma unroll
        for (int c = 0; c < 8; c++) {
            float vv = acc[r][c];
#pragma unroll
            for (int off = 16; off; off >>= 1) vv += __shfl_down_sync(0xffffffffu, vv, off);
            if (lane == 0) sred[warp][r * 8 + c] = vv;
        }
    __syncthreads();
    if (tid < 64) {
        float v = 0.f;
#pragma unroll
        for (int w = 0; w < 8; w++) v += sred[w][tid];
        int c = tid & 7;
        v += b2[c];
        float mx = v;
#pragma unroll
        for (int off = 4; off; off >>= 1) mx = fmaxf(mx, __shfl_xor_sync(0xffffffffu, mx, off, 8));
        float e = expf(v - mx);
        float s = e;
#pragma unroll
        for (int off = 4; off; off >>= 1) s += __shfl_xor_sync(0xffffffffu, s, off, 8);
        out[(size_t)(r0 + (tid >> 3)) * 8 + c] = e / s;
    }
}

// ---------------- host side ----------------
static float* symaddr(const void* sym) {
    void* p = nullptr;
    cudaGetSymbolAddress(&p, sym);
    return (float*)p;
}

extern "C" void kernel_launch(void* const* d_in, const int* in_sizes, int n_in,
                              void* d_out, int out_size) {
    const float* adj0 = (const float*)d_in[0];
    const float* adj1 = (const float*)d_in[1];
    const float* adj2 = (const float*)d_in[2];
    const float* feats = (const float*)d_in[3];
    const float* Wa1 = (const float*)d_in[4];
    const float* ba1 = (const float*)d_in[5];
    const float* Wa2 = (const float*)d_in[6];
    const float* ba2 = (const float*)d_in[7];
    const float* Wa3 = (const float*)d_in[8];
    const float* ba3 = (const float*)d_in[9];
    const float* Wagg = (const float*)d_in[10];
    const float* bagg = (const float*)d_in[11];
    const float* W1 = (const float*)d_in[12];
    const float* b1 = (const float*)d_in[13];
    const float* Wq = (const float*)d_in[14];
    const float* bq = (const float*)d_in[15];
    const float* Wk = (const float*)d_in[16];
    const float* bk = (const float*)d_in[17];
    const float* Wv = (const float*)d_in[18];
    const float* bv = (const float*)d_in[19];
    const float* W2 = (const float*)d_in[20];
    const float* b2 = (const float*)d_in[21];
    float* out = (float*)d_out;

    float* zcat = symaddr(g_zcat);
    float* adjp = symaddr(g_adj);
    float* fW1p = symaddr(g_fW1);
    float* xp   = symaddr(g_x);
    float* Qp   = symaddr(g_Q);
    float* Kp   = symaddr(g_K);
    float* Vp   = symaddr(g_V);
    float* attp = symaddr(g_att);
    float* xtp  = symaddr(g_xt);

    // L1: z_i = adj_i @ Wa_i + ba_i  (batched, 144 CTAs)
    GemmArgs a1{};
    a1.A[0] = adj0; a1.A[1] = adj1; a1.A[2] = adj2;
    a1.B[0] = Wa1;  a1.B[1] = Wa2;  a1.B[2] = Wa3;
    a1.C[0] = zcat; a1.C[1] = zcat + ADIM; a1.C[2] = zcat + 2 * ADIM;
    a1.bias[0] = ba1; a1.bias[1] = ba2; a1.bias[2] = ba3;
    a1.mul = nullptr;
    a1.M = NND; a1.N = ADIM; a1.K = NND; a1.lda = NND; a1.ldb = ADIM; a1.ldc = 384; a1.act = 0;
    sgemm_k<128, 128, 8, 8, 8, false><<<dim3(48, 1, 3), 256>>>(a1);

    // L2: gate softmax -> nz (also written straight to output region 2)
    int write_nz = (out_size >= NND * (NCLASS + 3)) ? 1 : 0;
    agg_softmax_k<<<768, 256>>>(Wagg, bagg, out + (size_t)NND * NCLASS, write_nz);

    // L3: fused adjacency
    build_adj_k<<<1184, 256>>>(adj0, adj1, adj2);

    // L4: fW1 = features @ W1
    GemmArgs a4{};
    a4.A[0] = a4.A[1] = a4.A[2] = feats;
    a4.B[0] = a4.B[1] = a4.B[2] = W1;
    a4.C[0] = a4.C[1] = a4.C[2] = fW1p;
    a4.bias[0] = a4.bias[1] = a4.bias[2] = nullptr;
    a4.mul = nullptr;
    a4.M = NND; a4.N = NHID; a4.K = NFEAT; a4.lda = NFEAT; a4.ldb = NHID; a4.ldc = NHID; a4.act = 0;
    sgemm_k<64, 128, 8, 8, 8, false><<<dim3(96, 2, 1), 128>>>(a4);

    // L5: x = relu(adj @ fW1 + b1)
    GemmArgs a5{};
    a5.A[0] = a5.A[1] = a5.A[2] = adjp;
    a5.B[0] = a5.B[1] = a5.B[2] = fW1p;
    a5.C[0] = a5.C[1] = a5.C[2] = xp;
    a5.bias[0] = a5.bias[1] = a5.bias[2] = b1;
    a5.mul = nullptr;
    a5.M = NND; a5.N = NHID; a5.K = NND; a5.lda = NND; a5.ldb = NHID; a5.ldc = NHID; a5.act = 1;
    sgemm_k<64, 128, 8, 8, 8, false><<<dim3(96, 2, 1), 128>>>(a5);

    // L6: Q/K/V = x @ W{q,k,v} + b  (batched)
    GemmArgs a6{};
    a6.A[0] = a6.A[1] = a6.A[2] = xp;
    a6.B[0] = Wq; a6.B[1] = Wk; a6.B[2] = Wv;
    a6.C[0] = Qp; a6.C[1] = Kp; a6.C[2] = Vp;
    a6.bias[0] = bq; a6.bias[1] = bk; a6.bias[2] = bv;
    a6.mul = nullptr;
    a6.M = NND; a6.N = NHID; a6.K = NHID; a6.lda = NHID; a6.ldb = NHID; a6.ldc = NHID; a6.act = 0;
    sgemm_k<64, 128, 8, 8, 8, false><<<dim3(96, 2, 3), 128>>>(a6);

    // L7: A_tilde = adj * (Q @ K^T)   (2304 CTAs)
    GemmArgs a7{};
    a7.A[0] = a7.A[1] = a7.A[2] = Qp;
    a7.B[0] = a7.B[1] = a7.B[2] = Kp;
    a7.C[0] = a7.C[1] = a7.C[2] = attp;
    a7.bias[0] = a7.bias[1] = a7.bias[2] = nullptr;
    a7.mul = adjp;
    a7.M = NND; a7.N = NND; a7.K = NHID; a7.lda = NHID; a7.ldb = NHID; a7.ldc = NND; a7.act = 0;
    sgemm_k<128, 128, 8, 8, 8, true><<<dim3(48, 48, 1), 256>>>(a7);

    // L8: row softmax (gcn_norm folds to identity at fp32 for softmax rows)
    attn_softmax_k<<<NND, 256>>>();

    // L9: X_tilde = relu(attention @ V)
    GemmArgs a9{};
    a9.A[0] = a9.A[1] = a9.A[2] = attp;
    a9.B[0] = a9.B[1] = a9.B[2] = Vp;
    a9.C[0] = a9.C[1] = a9.C[2] = xtp;
    a9.bias[0] = a9.bias[1] = a9.bias[2] = nullptr;
    a9.mul = nullptr;
    a9.M = NND; a9.N = NHID; a9.K = NND; a9.lda = NND; a9.ldb = NHID; a9.ldc = NHID; a9.act = 1;
    sgemm_k<64, 128, 8, 8, 8, false><<<dim3(96, 2, 1), 128>>>(a9);

    // L10: xtw2 = X_tilde @ W2
    xtw2_k<<<768, 256>>>(W2);

    // L11: z = adj @ xtw2 + b2 ; softmax over 8 classes -> out
    final_k<<<768, 256>>>(b2, out);
}

// round 3
// speedup vs baseline: 1.7042x; 1.7042x over previous
#include <cuda_runtime.h>
#include <cuda_bf16.h>
#include <math.h>
#include <stdint.h>

#define NND    6144
#define NFEAT  512
#define NHID   256
#define NCLASS 8
#define ADIM   128

// ---------------- device scratch (no allocations allowed) ----------------
__device__ float g_zcat[NND * 384];
__device__ float g_nzT[3 * NND];
__device__ float g_adj[(size_t)NND * NND];
__device__ float g_att[(size_t)NND * NND];
__device__ float g_WaT[3][(size_t)ADIM * NND];
__device__ float g_W1T[NHID * NFEAT];
__device__ float g_WqT[NHID * NHID];
__device__ float g_WkT[NHID * NHID];
__device__ float g_WvT[NHID * NHID];
__device__ float g_fW1T[(size_t)NHID * NND];
__device__ float g_VT[(size_t)NHID * NND];
__device__ float g_Q[(size_t)NND * NHID];
__device__ float g_Kh[(size_t)NND * NHID];
__device__ float g_x[(size_t)NND * NHID];
__device__ float g_xt[(size_t)NND * NHID];
__device__ float g_xtw2[NND * NCLASS];

// ---------------- helpers ----------------
__device__ __forceinline__ uint32_t s2u(const void* p) {
    uint32_t a;
    asm("{ .reg .u64 t; cvta.to.shared.u64 t, %1; cvt.u32.u64 %0, t; }" : "=r"(a) : "l"(p));
    return a;
}
__device__ __forceinline__ uint32_t pack2(__nv_bfloat16 a, __nv_bfloat16 b) {
    return (uint32_t)__bfloat16_as_ushort(a) | ((uint32_t)__bfloat16_as_ushort(b) << 16);
}

#define LDSM4(r, a)                                                                        \
    asm volatile("ldmatrix.sync.aligned.m8n8.x4.shared.b16 {%0,%1,%2,%3}, [%4];"           \
                 : "=r"((r)[0]), "=r"((r)[1]), "=r"((r)[2]), "=r"((r)[3]) : "r"(a))
#define LDSM2(r, a)                                                                        \
    asm volatile("ldmatrix.sync.aligned.m8n8.x2.shared.b16 {%0,%1}, [%2];"                 \
                 : "=r"((r)[0]), "=r"((r)[1]) : "r"(a))

__device__ __forceinline__ void mma16816(float c[4], const uint32_t a[4], const uint32_t b[2]) {
    asm volatile(
        "mma.sync.aligned.m16n8k16.row.col.f32.bf16.bf16.f32 "
        "{%0,%1,%2,%3}, {%4,%5,%6,%7}, {%8,%9}, {%0,%1,%2,%3};"
        : "+f"(c[0]), "+f"(c[1]), "+f"(c[2]), "+f"(c[3])
        : "r"(a[0]), "r"(a[1]), "r"(a[2]), "r"(a[3]), "r"(b[0]), "r"(b[1]));
}

// ---------------- mma.sync GEMM: C = act((A @ B'^T) * mul + bias) ----------------
// A: [M,K] row-major (lda).  B': [N,K] row-major (ldb).
// CTA tile 128x128, 8 warps, warp tile 64x32. KC=32 fp32/iter.
// bf16 3-term split: Ah*Bh + Ah*Bl + Al*Bh (fp32 accum).
struct TCArgs {
    const float* A[3];
    const float* B[3];     // transposed layout [N,K]
    float*       C[3];
    const float* bias[3];
    const float* mul;      // optional elementwise multiplier, layout [M,ldc]
    int M, N, K, lda, ldb, ldc, act;
    int tstore[3];         // 1: C stored transposed: C[col*M + m]
};

#define ROWB 80   // bytes per smem row (32 bf16 data + pad; 5r mod 8 -> conflict-free ldmatrix)

__global__ void __launch_bounds__(256, 1) mma_gemm(const TCArgs p) {
    __shared__ __align__(16) char sAH[128 * ROWB];
    __shared__ __align__(16) char sAL[128 * ROWB];
    __shared__ __align__(16) char sBH[128 * ROWB];
    __shared__ __align__(16) char sBL[128 * ROWB];

    const int bz = blockIdx.z;
    const float* __restrict__ A    = p.A[bz];
    const float* __restrict__ B    = p.B[bz];
    float* __restrict__       C    = p.C[bz];
    const float* __restrict__ bias = p.bias[bz];

    const int m0 = blockIdx.x * 128, n0 = blockIdx.y * 128;
    const int lda = p.lda, ldb = p.ldb, ldc = p.ldc, K = p.K;

    const int tid  = threadIdx.x;
    const int lane = tid & 31, wid = tid >> 5;
    const int wm = wid & 1, wn = wid >> 1;   // warp grid 2 x 4

    const uint32_t uAH = s2u(sAH), uAL = s2u(sAL), uBH = s2u(sBH), uBL = s2u(sBL);
    const uint32_t aRowOff = (uint32_t)((lane & 15) * ROWB + ((lane & 16) ? 16 : 0));
    const uint32_t bRowOff = (uint32_t)((lane & 7) * ROWB + ((lane & 8) ? 16 : 0));

    float acc[4][4][4];
#pragma unroll
    for (int mt = 0; mt < 4; mt++)
#pragma unroll
        for (int nt = 0; nt < 4; nt++)
#pragma unroll
            for (int q = 0; q < 4; q++) acc[mt][nt][q] = 0.f;

    const float* Abase = A + (size_t)m0 * lda;
    const float* Bbase = B + (size_t)n0 * ldb;

    float4 ra[4], rb[4];

    auto loadT = [&](const float* base, int ld, int k0, float4* r) {
#pragma unroll
        for (int l = 0; l < 4; l++) {
            int idx = tid + l * 256;
            int row = idx >> 3;
            int c4  = (idx & 7) << 2;
            r[l] = *reinterpret_cast<const float4*>(base + (size_t)row * ld + k0 + c4);
        }
    };
    auto storeT = [&](char* H, char* L, const float4* r) {
#pragma unroll
        for (int l = 0; l < 4; l++) {
            int idx = tid + l * 256;
            int row = idx >> 3;
            int c4  = (idx & 7) << 2;
            int off = row * ROWB + c4 * 2;
            float4 v = r[l];
            __nv_bfloat16 h0 = __float2bfloat16(v.x), h1 = __float2bfloat16(v.y);
            __nv_bfloat16 h2 = __float2bfloat16(v.z), h3 = __float2bfloat16(v.w);
            *reinterpret_cast<uint2*>(H + off) = make_uint2(pack2(h0, h1), pack2(h2, h3));
            *reinterpret_cast<uint2*>(L + off) = make_uint2(
                pack2(__float2bfloat16(v.x - __bfloat162float(h0)),
                      __float2bfloat16(v.y - __bfloat162float(h1))),
                pack2(__float2bfloat16(v.z - __bfloat162float(h2)),
                      __float2bfloat16(v.w - __bfloat162float(h3))));
        }
    };
    auto compute = [&]() {
#pragma unroll
        for (int pass = 0; pass < 3; pass++) {
            const uint32_t aBase = (pass < 2) ? uAH : uAL;
            const uint32_t bBase = (pass == 1) ? uBL : uBH;
#pragma unroll
            for (int ks = 0; ks < 2; ks++) {
                uint32_t af[4][4], bf_[4][2];
#pragma unroll
                for (int mt = 0; mt < 4; mt++)
                    LDSM4(af[mt], aBase + (uint32_t)((wm * 64 + mt * 16) * ROWB) + aRowOff +
                                      (uint32_t)(ks * 32));
#pragma unroll
                for (int nt = 0; nt < 4; nt++)
                    LDSM2(bf_[nt], bBase + (uint32_t)((wn * 32 + nt * 8) * ROWB) + bRowOff +
                                       (uint32_t)(ks * 32));
#pragma unroll
                for (int mt = 0; mt < 4; mt++)
#pragma unroll
                    for (int nt = 0; nt < 4; nt++) mma16816(acc[mt][nt], af[mt], bf_[nt]);
            }
        }
    };

    // prefetch pipeline: store(cur) -> sync -> issue loads(next) -> compute(cur) -> sync
    loadT(Abase, lda, 0, ra);
    loadT(Bbase, ldb, 0, rb);
    for (int k0 = 32; k0 < K; k0 += 32) {
        storeT(sAH, sAL, ra);
        storeT(sBH, sBL, rb);
        __syncthreads();
        loadT(Abase, lda, k0, ra);
        loadT(Bbase, ldb, k0, rb);
        compute();
        __syncthreads();
    }
    storeT(sAH, sAL, ra);
    storeT(sBH, sBL, rb);
    __syncthreads();
    compute();

    // ---------------- epilogue ----------------
    const int ts = p.tstore[bz];
    const float* __restrict__ mul = p.mul;
#pragma unroll
    for (int mt = 0; mt < 4; mt++) {
#pragma unroll
        for (int nt = 0; nt < 4; nt++) {
            int mA = m0 + wm * 64 + mt * 16 + (lane >> 2);
            int n  = n0 + wn * 32 + nt * 8 + 2 * (lane & 3);
#pragma unroll
            for (int h = 0; h < 2; h++) {
                int mm = mA + h * 8;
                float vx = acc[mt][nt][2 * h + 0];
                float vy = acc[mt][nt][2 * h + 1];
                if (mul) {
                    float2 mv = *reinterpret_cast<const float2*>(&mul[(size_t)mm * ldc + n]);
                    vx *= mv.x; vy *= mv.y;
                }
                if (bias) { vx += bias[n]; vy += bias[n + 1]; }
                if (p.act) { vx = fmaxf(vx, 0.f); vy = fmaxf(vy, 0.f); }
                if (!ts) {
                    *reinterpret_cast<float2*>(&C[(size_t)mm * ldc + n]) = make_float2(vx, vy);
                } else {
                    C[(size_t)n * p.M + mm]       = vx;
                    C[(size_t)(n + 1) * p.M + mm] = vy;
                }
            }
        }
    }
}

// ---------------- transpose: out[c][r] = in[r][c] ----------------
__global__ void transpose_k(const float* __restrict__ in, float* __restrict__ out,
                            int R, int C) {
    __shared__ float t[32][33];
    int c0 = blockIdx.x * 32, r0 = blockIdx.y * 32;
    int x = threadIdx.x, y = threadIdx.y;
#pragma unroll
    for (int i = 0; i < 32; i += 8) t[y + i][x] = in[(size_t)(r0 + y + i) * C + c0 + x];
    __syncthreads();
#pragma unroll
    for (int i = 0; i < 32; i += 8)
        out[(size_t)(c0 + y + i) * R + r0 + x] = t[x][y + i];
}

// ---------------- gate: z4 = zcat @ Wagg + bagg ; nz = softmax(z4) ----------------
__global__ void agg_softmax_k(const float* __restrict__ Wagg, const float* __restrict__ bagg,
                              float* __restrict__ out_nz, int write_out) {
    int row  = blockIdx.x * (blockDim.x / 32) + (threadIdx.x >> 5);
    int lane = threadIdx.x & 31;
    if (row >= NND) return;
    const float* z = &g_zcat[(size_t)row * 384];
    float s0 = 0.f, s1 = 0.f, s2 = 0.f;
    for (int k = lane; k < 384; k += 32) {
        float v = z[k];
        s0 = fmaf(v, Wagg[k * 3 + 0], s0);
        s1 = fmaf(v, Wagg[k * 3 + 1], s1);
        s2 = fmaf(v, Wagg[k * 3 + 2], s2);
    }
#pragma unroll
    for (int off = 16; off; off >>= 1) {
        s0 += __shfl_down_sync(0xffffffffu, s0, off);
        s1 += __shfl_down_sync(0xffffffffu, s1, off);
        s2 += __shfl_down_sync(0xffffffffu, s2, off);
    }
    if (lane == 0) {
        s0 += bagg[0]; s1 += bagg[1]; s2 += bagg[2];
        float mx = fmaxf(s0, fmaxf(s1, s2));
        float e0 = expf(s0 - mx), e1 = expf(s1 - mx), e2 = expf(s2 - mx);
        float inv = 1.f / (e0 + e1 + e2);
        e0 *= inv; e1 *= inv; e2 *= inv;
        g_nzT[0 * NND + row] = e0;
        g_nzT[1 * NND + row] = e1;
        g_nzT[2 * NND + row] = e2;
        if (write_out) {
            out_nz[row * 3 + 0] = e0;
            out_nz[row * 3 + 1] = e1;
            out_nz[row * 3 + 2] = e2;
        }
    }
}

// ---------------- adj[i,j] = nz[j,0]*a0 + nz[j,1]*a1 + nz[j,2]*a2 ----------------
__global__ void build_adj_k(const float* __restrict__ a0, const float* __restrict__ a1,
                            const float* __restrict__ a2) {
    const size_t total4 = (size_t)NND * NND / 4;
    for (size_t e = (size_t)blockIdx.x * blockDim.x + threadIdx.x; e < total4;
         e += (size_t)gridDim.x * blockDim.x) {
        size_t off = e * 4;
        int j = (int)(off % NND);
        float4 w0 = *reinterpret_cast<const float4*>(&g_nzT[j]);
        float4 w1 = *reinterpret_cast<const float4*>(&g_nzT[NND + j]);
        float4 w2 = *reinterpret_cast<const float4*>(&g_nzT[2 * NND + j]);
        float4 x0 = *reinterpret_cast<const float4*>(a0 + off);
        float4 x1 = *reinterpret_cast<const float4*>(a1 + off);
        float4 x2 = *reinterpret_cast<const float4*>(a2 + off);
        float4 r;
        r.x = w0.x * x0.x + w1.x * x1.x + w2.x * x2.x;
        r.y = w0.y * x0.y + w1.y * x1.y + w2.y * x2.y;
        r.z = w0.z * x0.z + w1.z * x1.z + w2.z * x2.z;
        r.w = w0.w * x0.w + w1.w * x1.w + w2.w * x2.w;
        *reinterpret_cast<float4*>(&g_adj[off]) = r;
    }
}

// ---------------- per-row softmax over the 6144-wide attention matrix -----------
__global__ void attn_softmax_k() {
    const int row = blockIdx.x;
    float* __restrict__ ptr = &g_att[(size_t)row * NND];
    const int tid  = threadIdx.x;
    const int lane = tid & 31, warp = tid >> 5;
    float4 v[6];
    float mx = -3.4e38f;
#pragma unroll
    for (int l = 0; l < 6; l++) {
        v[l] = *reinterpret_cast<const float4*>(&ptr[(tid + l * 256) * 4]);
        mx = fmaxf(mx, fmaxf(fmaxf(v[l].x, v[l].y), fmaxf(v[l].z, v[l].w)));
    }
    __shared__ float sm[8], ss[8];
#pragma unroll
    for (int off = 16; off; off >>= 1) mx = fmaxf(mx, __shfl_xor_sync(0xffffffffu, mx, off));
    if (lane == 0) sm[warp] = mx;
    __syncthreads();
    float bm = fmaxf(fmaxf(fmaxf(sm[0], sm[1]), fmaxf(sm[2], sm[3])),
                     fmaxf(fmaxf(sm[4], sm[5]), fmaxf(sm[6], sm[7])));
    float sum = 0.f;
#pragma unroll
    for (int l = 0; l < 6; l++) {
        v[l].x = expf(v[l].x - bm);
        v[l].y = expf(v[l].y - bm);
        v[l].z = expf(v[l].z - bm);
        v[l].w = expf(v[l].w - bm);
        sum += v[l].x + v[l].y + v[l].z + v[l].w;
    }
#pragma unroll
    for (int off = 16; off; off >>= 1) sum += __shfl_xor_sync(0xffffffffu, sum, off);
    if (lane == 0) ss[warp] = sum;
    __syncthreads();
    float tot = ss[0] + ss[1] + ss[2] + ss[3] + ss[4] + ss[5] + ss[6] + ss[7];
    float scale = 1.f / tot;
#pragma unroll
    for (int l = 0; l < 6; l++) {
        v[l].x *= scale; v[l].y *= scale; v[l].z *= scale; v[l].w *= scale;
        *reinterpret_cast<float4*>(&ptr[(tid + l * 256) * 4]) = v[l];
    }
}

// ---------------- X_tilde @ W2 (skinny, N=8) ----------------
__global__ void xtw2_k(const float* __restrict__ W2) {
    int row  = blockIdx.x * 8 + (threadIdx.x >> 5);
    int lane = threadIdx.x & 31;
    if (row >= NND) return;
    const float* xr = &g_xt[(size_t)row * NHID];
    float acc[8] = {0, 0, 0, 0, 0, 0, 0, 0};
    for (int h = lane; h < NHID; h += 32) {
        float xv = xr[h];
        const float4* wp = reinterpret_cast<const float4*>(&W2[h * 8]);
        float4 wlo = wp[0], whi = wp[1];
        acc[0] = fmaf(xv, wlo.x, acc[0]);
        acc[1] = fmaf(xv, wlo.y, acc[1]);
        acc[2] = fmaf(xv, wlo.z, acc[2]);
        acc[3] = fmaf(xv, wlo.w, acc[3]);
        acc[4] = fmaf(xv, whi.x, acc[4]);
        acc[5] = fmaf(xv, whi.y, acc[5]);
        acc[6] = fmaf(xv, whi.z, acc[6]);
        acc[7] = fmaf(xv, whi.w, acc[7]);
    }
#pragma unroll
    for (int c = 0; c < 8; c++)
#pragma unroll
        for (int off = 16; off; off >>= 1) acc[c] += __shfl_down_sync(0xffffffffu, acc[c], off);
    if (lane == 0) {
#pragma unroll
        for (int c = 0; c < 8; c++) g_xtw2[row * 8 + c] = acc[c];
    }
}

// ---------------- z = adj @ xtw2 + b2 ; out = softmax(z, axis=1). 8 rows/CTA ----
__global__ void final_k(const float* __restrict__ b2, float* __restrict__ out) {
    const int r0  = blockIdx.x * 8;
    const int tid = threadIdx.x;
    float acc[8][8];
#pragma unroll
    for (int r = 0; r < 8; r++)
#pragma unroll
        for (int c = 0; c < 8; c++) acc[r][c] = 0.f;

    for (int j4 = tid; j4 < NND / 4; j4 += 256) {
        float4 w[8];
        const float4* wp = reinterpret_cast<const float4*>(&g_xtw2[(size_t)j4 * 32]);
#pragma unroll
        for (int q = 0; q < 8; q++) w[q] = wp[q];
#pragma unroll
        for (int r = 0; r < 8; r++) {
            float4 a = *reinterpret_cast<const float4*>(&g_adj[(size_t)(r0 + r) * NND + j4 * 4]);
            float av[4] = {a.x, a.y, a.z, a.w};
#pragma unroll
            for (int q = 0; q < 4; q++) {
                acc[r][0] = fmaf(av[q], w[2 * q].x, acc[r][0]);
                acc[r][1] = fmaf(av[q], w[2 * q].y, acc[r][1]);
                acc[r][2] = fmaf(av[q], w[2 * q].z, acc[r][2]);
                acc[r][3] = fmaf(av[q], w[2 * q].w, acc[r][3]);
                acc[r][4] = fmaf(av[q], w[2 * q + 1].x, acc[r][4]);
                acc[r][5] = fmaf(av[q], w[2 * q + 1].y, acc[r][5]);
                acc[r][6] = fmaf(av[q], w[2 * q + 1].z, acc[r][6]);
                acc[r][7] = fmaf(av[q], w[2 * q + 1].w, acc[r][7]);
            }
        }
    }

    __shared__ float sred[8][64];
    const int lane = tid & 31, warp = tid >> 5;
#pragma unroll
    for (int r = 0; r < 8; r++)
#pragma unroll
        for (int c = 0; c < 8; c++) {
            float vv = acc[r][c];
#pragma unroll
            for (int off = 16; off; off >>= 1) vv += __shfl_down_sync(0xffffffffu, vv, off);
            if (lane == 0) sred[warp][r * 8 + c] = vv;
        }
    __syncthreads();
    if (tid < 64) {
        float v = 0.f;
#pragma unroll
        for (int w = 0; w < 8; w++) v += sred[w][tid];
        int c = tid & 7;
        v += b2[c];
        float mx = v;
#pragma unroll
        for (int off = 4; off; off >>= 1) mx = fmaxf(mx, __shfl_xor_sync(0xffffffffu, mx, off, 8));
        float e = expf(v - mx);
        float s = e;
#pragma unroll
        for (int off = 4; off; off >>= 1) s += __shfl_xor_sync(0xffffffffu, s, off, 8);
        out[(size_t)(r0 + (tid >> 3)) * 8 + c] = e / s;
    }
}

// ---------------- host side ----------------
static float* symaddr(const void* sym) {
    void* p = nullptr;
    cudaGetSymbolAddress(&p, sym);
    return (float*)p;
}

extern "C" void kernel_launch(void* const* d_in, const int* in_sizes, int n_in,
                              void* d_out, int out_size) {
    const float* adj0 = (const float*)d_in[0];
    const float* adj1 = (const float*)d_in[1];
    const float* adj2 = (const float*)d_in[2];
    const float* feats = (const float*)d_in[3];
    const float* Wa1 = (const float*)d_in[4];
    const float* ba1 = (const float*)d_in[5];
    const float* Wa2 = (const float*)d_in[6];
    const float* ba2 = (const float*)d_in[7];
    const float* Wa3 = (const float*)d_in[8];
    const float* ba3 = (const float*)d_in[9];
    const float* Wagg = (const float*)d_in[10];
    const float* bagg = (const float*)d_in[11];
    const float* W1 = (const float*)d_in[12];
    const float* b1 = (const float*)d_in[13];
    const float* Wq = (const float*)d_in[14];
    const float* bq = (const float*)d_in[15];
    const float* Wk = (const float*)d_in[16];
    const float* bk = (const float*)d_in[17];
    const float* Wv = (const float*)d_in[18];
    const float* bv = (const float*)d_in[19];
    const float* W2 = (const float*)d_in[20];
    const float* b2 = (const float*)d_in[21];
    float* out = (float*)d_out;

    float* zcat  = symaddr(g_zcat);
    float* adjp  = symaddr(g_adj);
    float* attp  = symaddr(g_att);
    float* WaTp  = symaddr(g_WaT);
    float* W1Tp  = symaddr(g_W1T);
    float* WqTp  = symaddr(g_WqT);
    float* WkTp  = symaddr(g_WkT);
    float* WvTp  = symaddr(g_WvT);
    float* fW1Tp = symaddr(g_fW1T);
    float* VTp   = symaddr(g_VT);
    float* Qp    = symaddr(g_Q);
    float* Kp    = symaddr(g_Kh);
    float* xp    = symaddr(g_x);
    float* xtp   = symaddr(g_xt);

    // transposes: Wa_i [N x ADIM] -> [ADIM x N]; W1; Wq/Wk/Wv
    transpose_k<<<dim3(ADIM / 32, NND / 32), dim3(32, 8)>>>(Wa1, WaTp + 0 * (size_t)ADIM * NND, NND, ADIM);
    transpose_k<<<dim3(ADIM / 32, NND / 32), dim3(32, 8)>>>(Wa2, WaTp + 1 * (size_t)ADIM * NND, NND, ADIM);
    transpose_k<<<dim3(ADIM / 32, NND / 32), dim3(32, 8)>>>(Wa3, WaTp + 2 * (size_t)ADIM * NND, NND, ADIM);
    transpose_k<<<dim3(NHID / 32, NFEAT / 32), dim3(32, 8)>>>(W1, W1Tp, NFEAT, NHID);
    transpose_k<<<dim3(NHID / 32, NHID / 32), dim3(32, 8)>>>(Wq, WqTp, NHID, NHID);
    transpose_k<<<dim3(NHID / 32, NHID / 32), dim3(32, 8)>>>(Wk, WkTp, NHID, NHID);
    transpose_k<<<dim3(NHID / 32, NHID / 32), dim3(32, 8)>>>(Wv, WvTp, NHID, NHID);

    // L1: z_i = adj_i @ Wa_i + ba_i  (batched) -> zcat columns
    {
        TCArgs a{};
        a.A[0] = adj0; a.A[1] = adj1; a.A[2] = adj2;
        a.B[0] = WaTp; a.B[1] = WaTp + (size_t)ADIM * NND; a.B[2] = WaTp + 2 * (size_t)ADIM * NND;
        a.C[0] = zcat; a.C[1] = zcat + ADIM; a.C[2] = zcat + 2 * ADIM;
        a.bias[0] = ba1; a.bias[1] = ba2; a.bias[2] = ba3;
        a.M = NND; a.N = ADIM; a.K = NND; a.lda = NND; a.ldb = NND; a.ldc = 384; a.act = 0;
        mma_gemm<<<dim3(48, 1, 3), 256>>>(a);
    }

    int write_nz = (out_size >= NND * (NCLASS + 3)) ? 1 : 0;
    agg_softmax_k<<<768, 256>>>(Wagg, bagg, out + (size_t)NND * NCLASS, write_nz);
    build_adj_k<<<1184, 256>>>(adj0, adj1, adj2);

    // L4: fW1^T = (feats @ W1)^T
    {
        TCArgs a{};
        a.A[0] = a.A[1] = a.A[2] = feats;
        a.B[0] = a.B[1] = a.B[2] = W1Tp;
        a.C[0] = a.C[1] = a.C[2] = fW1Tp;
        a.bias[0] = a.bias[1] = a.bias[2] = nullptr;
        a.M = NND; a.N = NHID; a.K = NFEAT; a.lda = NFEAT; a.ldb = NFEAT; a.ldc = NHID; a.act = 0;
        a.tstore[0] = a.tstore[1] = a.tstore[2] = 1;
        mma_gemm<<<dim3(48, 2, 1), 256>>>(a);
    }

    // L5: x = relu(adj @ fW1 + b1)
    {
        TCArgs a{};
        a.A[0] = a.A[1] = a.A[2] = adjp;
        a.B[0] = a.B[1] = a.B[2] = fW1Tp;
        a.C[0] = a.C[1] = a.C[2] = xp;
        a.bias[0] = a.bias[1] = a.bias[2] = b1;
        a.M = NND; a.N = NHID; a.K = NND; a.lda = NND; a.ldb = NND; a.ldc = NHID; a.act = 1;
        mma_gemm<<<dim3(48, 2, 1), 256>>>(a);
    }

    // L6: Q/K normal; V stored transposed
    {
        TCArgs a{};
        a.A[0] = a.A[1] = a.A[2] = xp;
        a.B[0] = WqTp; a.B[1] = WkTp; a.B[2] = WvTp;
        a.C[0] = Qp; a.C[1] = Kp; a.C[2] = VTp;
        a.bias[0] = bq; a.bias[1] = bk; a.bias[2] = bv;
        a.M = NND; a.N = NHID; a.K = NHID; a.lda = NHID; a.ldb = NHID; a.ldc = NHID; a.act = 0;
        a.tstore[0] = 0; a.tstore[1] = 0; a.tstore[2] = 1;
        mma_gemm<<<dim3(48, 2, 3), 256>>>(a);
    }

    // L7: A_tilde = adj * (Q @ K^T)
    {
        TCArgs a{};
        a.A[0] = a.A[1] = a.A[2] = Qp;
        a.B[0] = a.B[1] = a.B[2] = Kp;
        a.C[0] = a.C[1] = a.C[2] = attp;
        a.bias[0] = a.bias[1] = a.bias[2] = nullptr;
        a.mul = adjp;
        a.M = NND; a.N = NND; a.K = NHID; a.lda = NHID; a.ldb = NHID; a.ldc = NND; a.act = 0;
        mma_gemm<<<dim3(48, 48, 1), 256>>>(a);
    }

    attn_softmax_k<<<NND, 256>>>();

    // L9: X_tilde = relu(attention @ V)
    {
        TCArgs a{};
        a.A[0] = a.A[1] = a.A[2] = attp;
        a.B[0] = a.B[1] = a.B[2] = VTp;
        a.C[0] = a.C[1] = a.C[2] = xtp;
        a.bias[0] = a.bias[1] = a.bias[2] = nullptr;
        a.M = NND; a.N = NHID; a.K = NND; a.lda = NND; a.ldb = NND; a.ldc = NHID; a.act = 1;
        mma_gemm<<<dim3(48, 2, 1), 256>>>(a);
    }

    xtw2_k<<<768, 256>>>(W2);
    final_k<<<768, 256>>>(b2, out);
}

// round 4
// speedup vs baseline: 1.9404x; 1.1386x over previous
#include <cuda_runtime.h>
#include <cuda_bf16.h>
#include <math.h>
#include <stdint.h>

#define NND    6144
#define NFEAT  512
#define NHID   256
#define NCLASS 8
#define ADIM   128

// ---------------- device scratch (no allocations allowed) ----------------
__device__ float g_zcat[NND * 384];
__device__ float g_nzT[3 * NND];
__device__ float g_adj[(size_t)NND * NND];
__device__ float g_att[(size_t)NND * NND];
__device__ float g_WaT[3][(size_t)ADIM * NND];
__device__ float g_W1T[NHID * NFEAT];
__device__ float g_WqT[NHID * NHID];
__device__ float g_WkT[NHID * NHID];
__device__ float g_WvT[NHID * NHID];
__device__ float g_fW1T[(size_t)NHID * NND];
__device__ float g_VT[(size_t)NHID * NND];
__device__ float g_Q[(size_t)NND * NHID];
__device__ float g_Kh[(size_t)NND * NHID];
__device__ float g_x[(size_t)NND * NHID];
__device__ float g_xt[(size_t)NND * NHID];
__device__ float g_xtw2[NND * NCLASS];

// ---------------- helpers ----------------
__device__ __forceinline__ uint32_t s2u(const void* p) {
    uint32_t a;
    asm("{ .reg .u64 t; cvta.to.shared.u64 t, %1; cvt.u32.u64 %0, t; }" : "=r"(a) : "l"(p));
    return a;
}

#define LDSM4(r, a)                                                                        \
    asm volatile("ldmatrix.sync.aligned.m8n8.x4.shared.b16 {%0,%1,%2,%3}, [%4];"           \
                 : "=r"((r)[0]), "=r"((r)[1]), "=r"((r)[2]), "=r"((r)[3]) : "r"(a))
#define LDSM2(r, a)                                                                        \
    asm volatile("ldmatrix.sync.aligned.m8n8.x2.shared.b16 {%0,%1}, [%2];"                 \
                 : "=r"((r)[0]), "=r"((r)[1]) : "r"(a))

__device__ __forceinline__ void mma16816(float c[4], const uint32_t a[4], const uint32_t b[2]) {
    asm volatile(
        "mma.sync.aligned.m16n8k16.row.col.f32.bf16.bf16.f32 "
        "{%0,%1,%2,%3}, {%4,%5,%6,%7}, {%8,%9}, {%0,%1,%2,%3};"
        : "+f"(c[0]), "+f"(c[1]), "+f"(c[2]), "+f"(c[3])
        : "r"(a[0]), "r"(a[1]), "r"(a[2]), "r"(a[3]), "r"(b[0]), "r"(b[1]));
}

// split (x,y) -> packed bf16x2 hi, packed bf16x2 lo residual
__device__ __forceinline__ void cvt_split2(float x, float y, uint32_t& hi, uint32_t& lo) {
    __nv_bfloat162 h = __float22bfloat162_rn(make_float2(x, y));  // .x = low half
    hi = *reinterpret_cast<uint32_t*>(&h);
    float hx = __uint_as_float(hi << 16);
    float hy = __uint_as_float(hi & 0xFFFF0000u);
    __nv_bfloat162 l = __float22bfloat162_rn(make_float2(x - hx, y - hy));
    lo = *reinterpret_cast<uint32_t*>(&l);
}

// ---------------- mma.sync GEMM: C = act((A @ B'^T) * mul + bias) ----------------
// A: [M,K] row-major (lda).  B': [N,K] row-major (ldb).
// CTA tile 128x128, 8 warps, warp tile 64x32. KC=32 fp32/iter.
// bf16 3-term split: Ah*Bh + Ah*Bl + Al*Bh (fp32 accum).
// Double-buffered SMEM, one __syncthreads per iter; fill overlapped with MMA issue.
struct TCArgs {
    const float* A[3];
    const float* B[3];     // transposed layout [N,K]
    float*       C[3];
    const float* bias[3];
    const float* mul;      // optional elementwise multiplier, layout [M,ldc]
    int M, N, K, lda, ldb, ldc, act;
    int tstore[3];         // 1: C stored transposed: C[col*M + m]
};

#define ROWB 80                       // smem row stride (32 bf16 + pad, conflict-free ldmatrix)
#define TILEB (128 * ROWB)            // one bf16 tile: 10240 B
#define STAGEB (4 * TILEB)            // AH AL BH BL: 40960 B
#define GSMEM (2 * STAGEB)            // 81920 B dynamic

__global__ void __launch_bounds__(256, 1) mma_gemm(const TCArgs p) {
    extern __shared__ __align__(16) char smem[];

    const int bz = blockIdx.z;
    const float* __restrict__ A    = p.A[bz];
    const float* __restrict__ B    = p.B[bz];
    float* __restrict__       C    = p.C[bz];
    const float* __restrict__ bias = p.bias[bz];

    const int m0 = blockIdx.x * 128, n0 = blockIdx.y * 128;
    const int lda = p.lda, ldb = p.ldb, ldc = p.ldc, K = p.K;

    const int tid  = threadIdx.x;
    const int lane = tid & 31, wid = tid >> 5;
    const int wm = wid & 1, wn = wid >> 1;   // warp grid 2 x 4

    const uint32_t u0 = s2u(smem);
    const uint32_t aRowOff = (uint32_t)((lane & 15) * ROWB + ((lane & 16) ? 16 : 0));
    const uint32_t bRowOff = (uint32_t)((lane & 7) * ROWB + ((lane & 8) ? 16 : 0));

    float acc[4][4][4];
#pragma unroll
    for (int mt = 0; mt < 4; mt++)
#pragma unroll
        for (int nt = 0; nt < 4; nt++)
#pragma unroll
            for (int q = 0; q < 4; q++) acc[mt][nt][q] = 0.f;

    const float* Abase = A + (size_t)m0 * lda;
    const float* Bbase = B + (size_t)n0 * ldb;

    float4 ra[4], rb[4];

    // per-thread fill geometry: idx = tid + l*256; row = idx>>3; c4 = (idx&7)*4
    auto loadT = [&](int k0) {
#pragma unroll
        for (int l = 0; l < 4; l++) {
            int idx = tid + l * 256;
            int row = idx >> 3;
            int c4  = (idx & 7) << 2;
            ra[l] = *reinterpret_cast<const float4*>(Abase + (size_t)row * lda + k0 + c4);
            rb[l] = *reinterpret_cast<const float4*>(Bbase + (size_t)row * ldb + k0 + c4);
        }
    };
    auto storeT = [&](int stage) {
        char* AH = smem + stage * STAGEB;
        char* AL = AH + TILEB;
        char* BH = AL + TILEB;
        char* BL = BH + TILEB;
#pragma unroll
        for (int l = 0; l < 4; l++) {
            int idx = tid + l * 256;
            int row = idx >> 3;
            int off = row * ROWB + ((idx & 7) << 3);
            uint32_t h0, l0, h1, l1;
            cvt_split2(ra[l].x, ra[l].y, h0, l0);
            cvt_split2(ra[l].z, ra[l].w, h1, l1);
            *reinterpret_cast<uint2*>(AH + off) = make_uint2(h0, h1);
            *reinterpret_cast<uint2*>(AL + off) = make_uint2(l0, l1);
            cvt_split2(rb[l].x, rb[l].y, h0, l0);
            cvt_split2(rb[l].z, rb[l].w, h1, l1);
            *reinterpret_cast<uint2*>(BH + off) = make_uint2(h0, h1);
            *reinterpret_cast<uint2*>(BL + off) = make_uint2(l0, l1);
        }
    };
    auto compute = [&](int stage) {
        const uint32_t uAH = u0 + (uint32_t)(stage * STAGEB);
        const uint32_t uAL = uAH + TILEB;
        const uint32_t uBH = uAL + TILEB;
        const uint32_t uBL = uBH + TILEB;
#pragma unroll
        for (int pass = 0; pass < 3; pass++) {
            const uint32_t aBase = (pass < 2) ? uAH : uAL;
            const uint32_t bBase = (pass == 1) ? uBL : uBH;
#pragma unroll
            for (int ks = 0; ks < 2; ks++) {
                uint32_t af[4][4], bf_[4][2];
#pragma unroll
                for (int mt = 0; mt < 4; mt++)
                    LDSM4(af[mt], aBase + (uint32_t)((wm * 64 + mt * 16) * ROWB) + aRowOff +
                                      (uint32_t)(ks * 32));
#pragma unroll
                for (int nt = 0; nt < 4; nt++)
                    LDSM2(bf_[nt], bBase + (uint32_t)((wn * 32 + nt * 8) * ROWB) + bRowOff +
                                       (uint32_t)(ks * 32));
#pragma unroll
                for (int mt = 0; mt < 4; mt++)
#pragma unroll
                    for (int nt = 0; nt < 4; nt++) mma16816(acc[mt][nt], af[mt], bf_[nt]);
            }
        }
    };

    const int niter = K >> 5;
    // prologue: slab0 -> buf0; issue loads of slab1
    loadT(0);
    storeT(0);
    if (niter > 1) loadT(32);
    __syncthreads();
    for (int i = 0; i < niter; i++) {
        if (i + 1 < niter) storeT((i + 1) & 1);       // consumes regs (slab i+1)
        if (i + 2 < niter) loadT((i + 2) << 5);       // issue loads (slab i+2)
        compute(i & 1);
        __syncthreads();
    }

    // ---------------- epilogue ----------------
    const int ts = p.tstore[bz];
    const float* __restrict__ mul = p.mul;
#pragma unroll
    for (int mt = 0; mt < 4; mt++) {
#pragma unroll
        for (int nt = 0; nt < 4; nt++) {
            int mA = m0 + wm * 64 + mt * 16 + (lane >> 2);
            int n  = n0 + wn * 32 + nt * 8 + 2 * (lane & 3);
#pragma unroll
            for (int h = 0; h < 2; h++) {
                int mm = mA + h * 8;
                float vx = acc[mt][nt][2 * h + 0];
                float vy = acc[mt][nt][2 * h + 1];
                if (mul) {
                    float2 mv = *reinterpret_cast<const float2*>(&mul[(size_t)mm * ldc + n]);
                    vx *= mv.x; vy *= mv.y;
                }
                if (bias) { vx += bias[n]; vy += bias[n + 1]; }
                if (p.act) { vx = fmaxf(vx, 0.f); vy = fmaxf(vy, 0.f); }
                if (!ts) {
                    *reinterpret_cast<float2*>(&C[(size_t)mm * ldc + n]) = make_float2(vx, vy);
                } else {
                    C[(size_t)n * p.M + mm]       = vx;
                    C[(size_t)(n + 1) * p.M + mm] = vy;
                }
            }
        }
    }
}

// ---------------- transpose: out[c][r] = in[r][c] ----------------
__global__ void transpose_k(const float* __restrict__ in, float* __restrict__ out,
                            int R, int C) {
    __shared__ float t[32][33];
    int c0 = blockIdx.x * 32, r0 = blockIdx.y * 32;
    int x = threadIdx.x, y = threadIdx.y;
#pragma unroll
    for (int i = 0; i < 32; i += 8) t[y + i][x] = in[(size_t)(r0 + y + i) * C + c0 + x];
    __syncthreads();
#pragma unroll
    for (int i = 0; i < 32; i += 8)
        out[(size_t)(c0 + y + i) * R + r0 + x] = t[x][y + i];
}

// ---------------- gate: z4 = zcat @ Wagg + bagg ; nz = softmax(z4) ----------------
__global__ void agg_softmax_k(const float* __restrict__ Wagg, const float* __restrict__ bagg,
                              float* __restrict__ out_nz, int write_out) {
    int row  = blockIdx.x * (blockDim.x / 32) + (threadIdx.x >> 5);
    int lane = threadIdx.x & 31;
    if (row >= NND) return;
    const float* z = &g_zcat[(size_t)row * 384];
    float s0 = 0.f, s1 = 0.f, s2 = 0.f;
    for (int k = lane; k < 384; k += 32) {
        float v = z[k];
        s0 = fmaf(v, Wagg[k * 3 + 0], s0);
        s1 = fmaf(v, Wagg[k * 3 + 1], s1);
        s2 = fmaf(v, Wagg[k * 3 + 2], s2);
    }
#pragma unroll
    for (int off = 16; off; off >>= 1) {
        s0 += __shfl_down_sync(0xffffffffu, s0, off);
        s1 += __shfl_down_sync(0xffffffffu, s1, off);
        s2 += __shfl_down_sync(0xffffffffu, s2, off);
    }
    if (lane == 0) {
        s0 += bagg[0]; s1 += bagg[1]; s2 += bagg[2];
        float mx = fmaxf(s0, fmaxf(s1, s2));
        float e0 = expf(s0 - mx), e1 = expf(s1 - mx), e2 = expf(s2 - mx);
        float inv = 1.f / (e0 + e1 + e2);
        e0 *= inv; e1 *= inv; e2 *= inv;
        g_nzT[0 * NND + row] = e0;
        g_nzT[1 * NND + row] = e1;
        g_nzT[2 * NND + row] = e2;
        if (write_out) {
            out_nz[row * 3 + 0] = e0;
            out_nz[row * 3 + 1] = e1;
            out_nz[row * 3 + 2] = e2;
        }
    }
}

// ---------------- adj[i,j] = nz[j,0]*a0 + nz[j,1]*a1 + nz[j,2]*a2 ----------------
__global__ void build_adj_k(const float* __restrict__ a0, const float* __restrict__ a1,
                            const float* __restrict__ a2) {
    const size_t total4 = (size_t)NND * NND / 4;
    for (size_t e = (size_t)blockIdx.x * blockDim.x + threadIdx.x; e < total4;
         e += (size_t)gridDim.x * blockDim.x) {
        size_t off = e * 4;
        int j = (int)(off % NND);
        float4 w0 = *reinterpret_cast<const float4*>(&g_nzT[j]);
        float4 w1 = *reinterpret_cast<const float4*>(&g_nzT[NND + j]);
        float4 w2 = *reinterpret_cast<const float4*>(&g_nzT[2 * NND + j]);
        float4 x0 = *reinterpret_cast<const float4*>(a0 + off);
        float4 x1 = *reinterpret_cast<const float4*>(a1 + off);
        float4 x2 = *reinterpret_cast<const float4*>(a2 + off);
        float4 r;
        r.x = w0.x * x0.x + w1.x * x1.x + w2.x * x2.x;
        r.y = w0.y * x0.y + w1.y * x1.y + w2.y * x2.y;
        r.z = w0.z * x0.z + w1.z * x1.z + w2.z * x2.z;
        r.w = w0.w * x0.w + w1.w * x1.w + w2.w * x2.w;
        *reinterpret_cast<float4*>(&g_adj[off]) = r;
    }
}

// ---------------- per-row softmax over the 6144-wide attention matrix -----------
__global__ void attn_softmax_k() {
    const int row = blockIdx.x;
    float* __restrict__ ptr = &g_att[(size_t)row * NND];
    const int tid  = threadIdx.x;
    const int lane = tid & 31, warp = tid >> 5;
    float4 v[6];
    float mx = -3.4e38f;
#pragma unroll
    for (int l = 0; l < 6; l++) {
        v[l] = *reinterpret_cast<const float4*>(&ptr[(tid + l * 256) * 4]);
        mx = fmaxf(mx, fmaxf(fmaxf(v[l].x, v[l].y), fmaxf(v[l].z, v[l].w)));
    }
    __shared__ float sm[8], ss[8];
#pragma unroll
    for (int off = 16; off; off >>= 1) mx = fmaxf(mx, __shfl_xor_sync(0xffffffffu, mx, off));
    if (lane == 0) sm[warp] = mx;
    __syncthreads();
    float bm = fmaxf(fmaxf(fmaxf(sm[0], sm[1]), fmaxf(sm[2], sm[3])),
                     fmaxf(fmaxf(sm[4], sm[5]), fmaxf(sm[6], sm[7])));
    float sum = 0.f;
#pragma unroll
    for (int l = 0; l < 6; l++) {
        v[l].x = expf(v[l].x - bm);
        v[l].y = expf(v[l].y - bm);
        v[l].z = expf(v[l].z - bm);
        v[l].w = expf(v[l].w - bm);
        sum += v[l].x + v[l].y + v[l].z + v[l].w;
    }
#pragma unroll
    for (int off = 16; off; off >>= 1) sum += __shfl_xor_sync(0xffffffffu, sum, off);
    if (lane == 0) ss[warp] = sum;
    __syncthreads();
    float tot = ss[0] + ss[1] + ss[2] + ss[3] + ss[4] + ss[5] + ss[6] + ss[7];
    float scale = 1.f / tot;
#pragma unroll
    for (int l = 0; l < 6; l++) {
        v[l].x *= scale; v[l].y *= scale; v[l].z *= scale; v[l].w *= scale;
        *reinterpret_cast<float4*>(&ptr[(tid + l * 256) * 4]) = v[l];
    }
}

// ---------------- X_tilde @ W2 (skinny, N=8) ----------------
__global__ void xtw2_k(const float* __restrict__ W2) {
    int row  = blockIdx.x * 8 + (threadIdx.x >> 5);
    int lane = threadIdx.x & 31;
    if (row >= NND) return;
    const float* xr = &g_xt[(size_t)row * NHID];
    float acc[8] = {0, 0, 0, 0, 0, 0, 0, 0};
    for (int h = lane; h < NHID; h += 32) {
        float xv = xr[h];
        const float4* wp = reinterpret_cast<const float4*>(&W2[h * 8]);
        float4 wlo = wp[0], whi = wp[1];
        acc[0] = fmaf(xv, wlo.x, acc[0]);
        acc[1] = fmaf(xv, wlo.y, acc[1]);
        acc[2] = fmaf(xv, wlo.z, acc[2]);
        acc[3] = fmaf(xv, wlo.w, acc[3]);
        acc[4] = fmaf(xv, whi.x, acc[4]);
        acc[5] = fmaf(xv, whi.y, acc[5]);
        acc[6] = fmaf(xv, whi.z, acc[6]);
        acc[7] = fmaf(xv, whi.w, acc[7]);
    }
#pragma unroll
    for (int c = 0; c < 8; c++)
#pragma unroll
        for (int off = 16; off; off >>= 1) acc[c] += __shfl_down_sync(0xffffffffu, acc[c], off);
    if (lane == 0) {
#pragma unroll
        for (int c = 0; c < 8; c++) g_xtw2[row * 8 + c] = acc[c];
    }
}

// ---------------- z = adj @ xtw2 + b2 ; out = softmax(z, axis=1). 8 rows/CTA ----
__global__ void final_k(const float* __restrict__ b2, float* __restrict__ out) {
    const int r0  = blockIdx.x * 8;
    const int tid = threadIdx.x;
    float acc[8][8];
#pragma unroll
    for (int r = 0; r < 8; r++)
#pragma unroll
        for (int c = 0; c < 8; c++) acc[r][c] = 0.f;

    for (int j4 = tid; j4 < NND / 4; j4 += 256) {
        float4 w[8];
        const float4* wp = reinterpret_cast<const float4*>(&g_xtw2[(size_t)j4 * 32]);
#pragma unroll
        for (int q = 0; q < 8; q++) w[q] = wp[q];
#pragma unroll
        for (int r = 0; r < 8; r++) {
            float4 a = *reinterpret_cast<const float4*>(&g_adj[(size_t)(r0 + r) * NND + j4 * 4]);
            float av[4] = {a.x, a.y, a.z, a.w};
#pragma unroll
            for (int q = 0; q < 4; q++) {
                acc[r][0] = fmaf(av[q], w[2 * q].x, acc[r][0]);
                acc[r][1] = fmaf(av[q], w[2 * q].y, acc[r][1]);
                acc[r][2] = fmaf(av[q], w[2 * q].z, acc[r][2]);
                acc[r][3] = fmaf(av[q], w[2 * q].w, acc[r][3]);
                acc[r][4] = fmaf(av[q], w[2 * q + 1].x, acc[r][4]);
                acc[r][5] = fmaf(av[q], w[2 * q + 1].y, acc[r][5]);
                acc[r][6] = fmaf(av[q], w[2 * q + 1].z, acc[r][6]);
                acc[r][7] = fmaf(av[q], w[2 * q + 1].w, acc[r][7]);
            }
        }
    }

    __shared__ float sred[8][64];
    const int lane = tid & 31, warp = tid >> 5;
#pragma unroll
    for (int r = 0; r < 8; r++)
#pragma unroll
        for (int c = 0; c < 8; c++) {
            float vv = acc[r][c];
#pragma unroll
            for (int off = 16; off; off >>= 1) vv += __shfl_down_sync(0xffffffffu, vv, off);
            if (lane == 0) sred[warp][r * 8 + c] = vv;
        }
    __syncthreads();
    if (tid < 64) {
        float v = 0.f;
#pragma unroll
        for (int w = 0; w < 8; w++) v += sred[w][tid];
        int c = tid & 7;
        v += b2[c];
        float mx = v;
#pragma unroll
        for (int off = 4; off; off >>= 1) mx = fmaxf(mx, __shfl_xor_sync(0xffffffffu, mx, off, 8));
        float e = expf(v - mx);
        float s = e;
#pragma unroll
        for (int off = 4; off; off >>= 1) s += __shfl_xor_sync(0xffffffffu, s, off, 8);
        out[(size_t)(r0 + (tid >> 3)) * 8 + c] = e / s;
    }
}

// ---------------- host side ----------------
static float* symaddr(const void* sym) {
    void* p = nullptr;
    cudaGetSymbolAddress(&p, sym);
    return (float*)p;
}

extern "C" void kernel_launch(void* const* d_in, const int* in_sizes, int n_in,
                              void* d_out, int out_size) {
    const float* adj0 = (const float*)d_in[0];
    const float* adj1 = (const float*)d_in[1];
    const float* adj2 = (const float*)d_in[2];
    const float* feats = (const float*)d_in[3];
    const float* Wa1 = (const float*)d_in[4];
    const float* ba1 = (const float*)d_in[5];
    const float* Wa2 = (const float*)d_in[6];
    const float* ba2 = (const float*)d_in[7];
    const float* Wa3 = (const float*)d_in[8];
    const float* ba3 = (const float*)d_in[9];
    const float* Wagg = (const float*)d_in[10];
    const float* bagg = (const float*)d_in[11];
    const float* W1 = (const float*)d_in[12];
    const float* b1 = (const float*)d_in[13];
    const float* Wq = (const float*)d_in[14];
    const float* bq = (const float*)d_in[15];
    const float* Wk = (const float*)d_in[16];
    const float* bk = (const float*)d_in[17];
    const float* Wv = (const float*)d_in[18];
    const float* bv = (const float*)d_in[19];
    const float* W2 = (const float*)d_in[20];
    const float* b2 = (const float*)d_in[21];
    float* out = (float*)d_out;

    float* zcat  = symaddr(g_zcat);
    float* adjp  = symaddr(g_adj);
    float* attp  = symaddr(g_att);
    float* WaTp  = symaddr(g_WaT);
    float* W1Tp  = symaddr(g_W1T);
    float* WqTp  = symaddr(g_WqT);
    float* WkTp  = symaddr(g_WkT);
    float* WvTp  = symaddr(g_WvT);
    float* fW1Tp = symaddr(g_fW1T);
    float* VTp   = symaddr(g_VT);
    float* Qp    = symaddr(g_Q);
    float* Kp    = symaddr(g_Kh);
    float* xp    = symaddr(g_x);
    float* xtp   = symaddr(g_xt);

    cudaFuncSetAttribute(mma_gemm, cudaFuncAttributeMaxDynamicSharedMemorySize, GSMEM);

    // transposes: Wa_i [N x ADIM] -> [ADIM x N]; W1; Wq/Wk/Wv
    transpose_k<<<dim3(ADIM / 32, NND / 32), dim3(32, 8)>>>(Wa1, WaTp + 0 * (size_t)ADIM * NND, NND, ADIM);
    transpose_k<<<dim3(ADIM / 32, NND / 32), dim3(32, 8)>>>(Wa2, WaTp + 1 * (size_t)ADIM * NND, NND, ADIM);
    transpose_k<<<dim3(ADIM / 32, NND / 32), dim3(32, 8)>>>(Wa3, WaTp + 2 * (size_t)ADIM * NND, NND, ADIM);
    transpose_k<<<dim3(NHID / 32, NFEAT / 32), dim3(32, 8)>>>(W1, W1Tp, NFEAT, NHID);
    transpose_k<<<dim3(NHID / 32, NHID / 32), dim3(32, 8)>>>(Wq, WqTp, NHID, NHID);
    transpose_k<<<dim3(NHID / 32, NHID / 32), dim3(32, 8)>>>(Wk, WkTp, NHID, NHID);
    transpose_k<<<dim3(NHID / 32, NHID / 32), dim3(32, 8)>>>(Wv, WvTp, NHID, NHID);

    // L1: z_i = adj_i @ Wa_i + ba_i  (batched) -> zcat columns
    {
        TCArgs a{};
        a.A[0] = adj0; a.A[1] = adj1; a.A[2] = adj2;
        a.B[0] = WaTp; a.B[1] = WaTp + (size_t)ADIM * NND; a.B[2] = WaTp + 2 * (size_t)ADIM * NND;
        a.C[0] = zcat; a.C[1] = zcat + ADIM; a.C[2] = zcat + 2 * ADIM;
        a.bias[0] = ba1; a.bias[1] = ba2; a.bias[2] = ba3;
        a.M = NND; a.N = ADIM; a.K = NND; a.lda = NND; a.ldb = NND; a.ldc = 384; a.act = 0;
        mma_gemm<<<dim3(48, 1, 3), 256, GSMEM>>>(a);
    }

    int write_nz = (out_size >= NND * (NCLASS + 3)) ? 1 : 0;
    agg_softmax_k<<<768, 256>>>(Wagg, bagg, out + (size_t)NND * NCLASS, write_nz);
    build_adj_k<<<1184, 256>>>(adj0, adj1, adj2);

    // L4: fW1^T = (feats @ W1)^T
    {
        TCArgs a{};
        a.A[0] = a.A[1] = a.A[2] = feats;
        a.B[0] = a.B[1] = a.B[2] = W1Tp;
        a.C[0] = a.C[1] = a.C[2] = fW1Tp;
        a.bias[0] = a.bias[1] = a.bias[2] = nullptr;
        a.M = NND; a.N = NHID; a.K = NFEAT; a.lda = NFEAT; a.ldb = NFEAT; a.ldc = NHID; a.act = 0;
        a.tstore[0] = a.tstore[1] = a.tstore[2] = 1;
        mma_gemm<<<dim3(48, 2, 1), 256, GSMEM>>>(a);
    }

    // L5: x = relu(adj @ fW1 + b1)
    {
        TCArgs a{};
        a.A[0] = a.A[1] = a.A[2] = adjp;
        a.B[0] = a.B[1] = a.B[2] = fW1Tp;
        a.C[0] = a.C[1] = a.C[2] = xp;
        a.bias[0] = a.bias[1] = a.bias[2] = b1;
        a.M = NND; a.N = NHID; a.K = NND; a.lda = NND; a.ldb = NND; a.ldc = NHID; a.act = 1;
        mma_gemm<<<dim3(48, 2, 1), 256, GSMEM>>>(a);
    }

    // L6: Q/K normal; V stored transposed
    {
        TCArgs a{};
        a.A[0] = a.A[1] = a.A[2] = xp;
        a.B[0] = WqTp; a.B[1] = WkTp; a.B[2] = WvTp;
        a.C[0] = Qp; a.C[1] = Kp; a.C[2] = VTp;
        a.bias[0] = bq; a.bias[1] = bk; a.bias[2] = bv;
        a.M = NND; a.N = NHID; a.K = NHID; a.lda = NHID; a.ldb = NHID; a.ldc = NHID; a.act = 0;
        a.tstore[0] = 0; a.tstore[1] = 0; a.tstore[2] = 1;
        mma_gemm<<<dim3(48, 2, 3), 256, GSMEM>>>(a);
    }

    // L7: A_tilde = adj * (Q @ K^T)
    {
        TCArgs a{};
        a.A[0] = a.A[1] = a.A[2] = Qp;
        a.B[0] = a.B[1] = a.B[2] = Kp;
        a.C[0] = a.C[1] = a.C[2] = attp;
        a.bias[0] = a.bias[1] = a.bias[2] = nullptr;
        a.mul = adjp;
        a.M = NND; a.N = NND; a.K = NHID; a.lda = NHID; a.ldb = NHID; a.ldc = NND; a.act = 0;
        mma_gemm<<<dim3(48, 48, 1), 256, GSMEM>>>(a);
    }

    attn_softmax_k<<<NND, 256>>>();

    // L9: X_tilde = relu(attention @ V)
    {
        TCArgs a{};
        a.A[0] = a.A[1] = a.A[2] = attp;
        a.B[0] = a.B[1] = a.B[2] = VTp;
        a.C[0] = a.C[1] = a.C[2] = xtp;
        a.bias[0] = a.bias[1] = a.bias[2] = nullptr;
        a.M = NND; a.N = NHID; a.K = NND; a.lda = NND; a.ldb = NND; a.ldc = NHID; a.act = 1;
        mma_gemm<<<dim3(48, 2, 1), 256, GSMEM>>>(a);
    }

    xtw2_k<<<768, 256>>>(W2);
    final_k<<<768, 256>>>(b2, out);
}